// round 2
// baseline (speedup 1.0000x reference)
#include <cuda_runtime.h>

#define N_NODES 50000
#define N_REL   3
#define D       128
#define N_EDGES 600000

// 3 * 50000 * 128 floats = 76.8 MB scratch for wh = x@W_r + b_r
__device__ float g_wh[(size_t)N_REL * N_NODES * D];
// 1 if src/dst are int32, 0 if int64
__device__ int g_idx32;

// ---------------------------------------------------------------------------
// Zero the output (harness poisons it to 0xAA) + reset dtype flag
// ---------------------------------------------------------------------------
__global__ void zero_out_kernel(float4* out, int n4) {
    int i = blockIdx.x * blockDim.x + threadIdx.x;
    if (i < n4) out[i] = make_float4(0.f, 0.f, 0.f, 0.f);
    if (i == 0) g_idx32 = 0;
}

// ---------------------------------------------------------------------------
// Index-dtype sniffer: if buffers are little-endian int64 with values
// < 2^31, every odd 32-bit word is 0. If ANY odd word is nonzero across
// 4096 samples of each array, the data must be int32.
// ---------------------------------------------------------------------------
__global__ void detect_idx_kernel(const unsigned int* __restrict__ src32,
                                  const unsigned int* __restrict__ dst32) {
    int t = blockIdx.x * blockDim.x + threadIdx.x;
    unsigned int any = 0;
    for (int i = t; i < 4096; i += 256)
        any |= src32[2 * i + 1] | dst32[2 * i + 1];
    any = __reduce_or_sync(0xFFFFFFFFu, any);
    if ((threadIdx.x & 31) == 0 && any)
        atomicOr(&g_idx32, 1);
}

// ---------------------------------------------------------------------------
// GEMM + bias: g_wh[r] = x @ W[r] + b[r]
// Tile: BM=64, BN=128 (full), BK=64 (2 k-tiles). 256 threads.
// Each thread computes 8 rows x 4 cols (float4 accumulators).
// smem = 48KB static. A-loads warp-broadcast; B-loads LDS.128 conflict-free.
// ---------------------------------------------------------------------------
__global__ __launch_bounds__(256) void gemm_bias_kernel(
    const float* __restrict__ x,
    const float* __restrict__ W,
    const float* __restrict__ b)
{
    __shared__ float xs[64 * 64];    // [row][k] k-tile
    __shared__ float ws[64 * 128];   // [k][col]

    const int r    = blockIdx.y;
    const int row0 = blockIdx.x * 64;
    const int tid  = threadIdx.x;
    const int tr   = tid >> 5;   // 0..7
    const int tc   = tid & 31;   // 0..31 (float4 column)

    const float4* x4 = (const float4*)x;
    const float4* w4 = (const float4*)(W + (size_t)r * D * D);

    float4 acc[8];
#pragma unroll
    for (int i = 0; i < 8; i++) acc[i] = make_float4(0.f, 0.f, 0.f, 0.f);

#pragma unroll
    for (int kt = 0; kt < 2; kt++) {
        // Load x tile: 64 rows x 16 float4 (this k-tile)
#pragma unroll
        for (int l = 0; l < 4; l++) {
            int i   = tid + l * 256;       // 0..1023
            int row = i >> 4;
            int c   = i & 15;
            float4 v = make_float4(0.f, 0.f, 0.f, 0.f);
            if (row0 + row < N_NODES)
                v = x4[(size_t)(row0 + row) * 32 + kt * 16 + c];
            ((float4*)xs)[i] = v;
        }
        // Load W tile: 64 k-rows x 32 float4
#pragma unroll
        for (int l = 0; l < 8; l++) {
            int i = tid + l * 256;         // 0..2047
            ((float4*)ws)[i] = w4[(size_t)kt * 64 * 32 + i];
        }
        __syncthreads();

#pragma unroll 16
        for (int k = 0; k < 64; k++) {
            float4 bv = ((const float4*)ws)[k * 32 + tc];
#pragma unroll
            for (int i = 0; i < 8; i++) {
                float a = xs[(tr * 8 + i) * 64 + k];
                acc[i].x += a * bv.x;
                acc[i].y += a * bv.y;
                acc[i].z += a * bv.z;
                acc[i].w += a * bv.w;
            }
        }
        __syncthreads();
    }

    float4 bias = ((const float4*)(b + (size_t)r * D))[tc];
#pragma unroll
    for (int i = 0; i < 8; i++) {
        int row = row0 + tr * 8 + i;
        if (row < N_NODES) {
            float4 v;
            v.x = acc[i].x + bias.x;
            v.y = acc[i].y + bias.y;
            v.z = acc[i].z + bias.z;
            v.w = acc[i].w + bias.w;
            ((float4*)g_wh)[((size_t)r * N_NODES + row) * 32 + tc] = v;
        }
    }
}

// ---------------------------------------------------------------------------
// Edge scatter: out[dst] += wh[r][src], one warp per edge.
// 32 lanes x float4 = 128 floats. Gather via __ldg (L2-resident wh),
// scatter via red.global.add.v4.f32 (no-return vectorized reduction).
// Index dtype resolved at runtime via g_idx32 (warp-uniform branch).
// ---------------------------------------------------------------------------
__global__ __launch_bounds__(256) void scatter_edges_kernel(
    const void* __restrict__ srcv,
    const void* __restrict__ dstv,
    float* __restrict__ out)
{
    const int r    = blockIdx.y;
    const int warp = threadIdx.x >> 5;
    const int lane = threadIdx.x & 31;

    long long e = (long long)blockIdx.x * 8 + warp;
    if (e >= N_EDGES) return;

    long long s, d;
    if (g_idx32) {
        s = ((const int*)srcv)[(size_t)r * N_EDGES + e];
        d = ((const int*)dstv)[(size_t)r * N_EDGES + e];
    } else {
        s = ((const long long*)srcv)[(size_t)r * N_EDGES + e];
        d = ((const long long*)dstv)[(size_t)r * N_EDGES + e];
    }
    if ((unsigned long long)s >= N_NODES || (unsigned long long)d >= N_NODES)
        return;  // crash insurance; never taken for valid inputs

    const float4* p = ((const float4*)g_wh) + ((size_t)r * N_NODES + s) * 32;
    float4 v = __ldg(p + lane);

    float* q = out + (size_t)d * D + lane * 4;
    asm volatile("red.global.add.v4.f32 [%0], {%1, %2, %3, %4};"
                 :: "l"(q), "f"(v.x), "f"(v.y), "f"(v.z), "f"(v.w)
                 : "memory");
}

// ---------------------------------------------------------------------------
// Launch
// ---------------------------------------------------------------------------
extern "C" void kernel_launch(void* const* d_in, const int* in_sizes, int n_in,
                              void* d_out, int out_size)
{
    const float* x   = (const float*)d_in[0];
    const float* W   = (const float*)d_in[1];
    const float* b   = (const float*)d_in[2];
    const void*  src = d_in[3];
    const void*  dst = d_in[4];
    float*       out = (float*)d_out;

    // Zero output (poisoned by harness) + reset dtype flag
    int n4 = N_NODES * D / 4;
    zero_out_kernel<<<(n4 + 255) / 256, 256>>>((float4*)out, n4);

    // Sniff index dtype (int32 vs int64)
    detect_idx_kernel<<<1, 256>>>((const unsigned int*)src,
                                  (const unsigned int*)dst);

    // wh[r] = x @ W[r] + b[r]
    dim3 ggrid((N_NODES + 63) / 64, N_REL);
    gemm_bias_kernel<<<ggrid, 256>>>(x, W, b);

    // out[dst] += wh[r][src]
    dim3 sgrid((N_EDGES + 7) / 8, N_REL);
    scatter_edges_kernel<<<sgrid, 256>>>(src, dst, out);
}